// round 1
// baseline (speedup 1.0000x reference)
#include <cuda_runtime.h>
#include <cuda_bf16.h>
#include <cstdint>

#define NUM_CLASSES 1000
#define D 512
#define N_MAX 131072

// ---------------- scratch (no allocations allowed) ----------------
__device__ int   g_counts[NUM_CLASSES];
__device__ int   g_offsets[NUM_CLASSES + 1];
__device__ int   g_cursor[NUM_CLASSES];
__device__ int   g_sorted[N_MAX];
__device__ float g_centers[NUM_CLASSES * D];
__device__ float g_sq[NUM_CLASSES];
__device__ int   g_minbits;   // float bits of min positive distance (positive floats order as ints)
__device__ int   g_lab64;     // 1 if labels are int64, 0 if int32

__device__ __forceinline__ int load_label(const void* labels, int i, int is64) {
    if (is64) return (int)((const long long*)labels)[i];
    return ((const int*)labels)[i];
}

// K0: reset per-call state
__global__ void k_init() {
    int t = threadIdx.x;
    if (t < NUM_CLASSES) g_counts[t] = 0;
    if (t == 0) {
        g_minbits = 0x7F800000;  // +inf
        g_lab64 = 1;
    }
}

// K1: dtype sniff — if labels are int32, int64 reinterpretation is out of range a.s.
__global__ void k_detect(const void* labels) {
    int t = threadIdx.x;  // 512 threads
    long long v = ((const long long*)labels)[t];
    if (v < 0 || v >= NUM_CLASSES) g_lab64 = 0;
}

// K2: histogram
__global__ void k_hist(const void* labels, int n) {
    int i = blockIdx.x * blockDim.x + threadIdx.x;
    int is64 = g_lab64;
    if (i < n) {
        int lab = load_label(labels, i, is64);
        atomicAdd(&g_counts[lab], 1);
    }
}

// K3: exclusive scan over 1000 counts (single block, 1024 threads)
__global__ void k_scan(int n) {
    __shared__ int s[1024];
    int t = threadIdx.x;
    int v = (t < NUM_CLASSES) ? g_counts[t] : 0;
    s[t] = v;
    __syncthreads();
#pragma unroll
    for (int off = 1; off < 1024; off <<= 1) {
        int add = (t >= off) ? s[t - off] : 0;
        __syncthreads();
        s[t] += add;
        __syncthreads();
    }
    int excl = s[t] - v;
    if (t < NUM_CLASSES) {
        g_offsets[t] = excl;
        g_cursor[t]  = excl;
    }
    if (t == 0) g_offsets[NUM_CLASSES] = n;
}

// K4: scatter row indices into class-sorted order
__global__ void k_scatter(const void* labels, int n) {
    int i = blockIdx.x * blockDim.x + threadIdx.x;
    int is64 = g_lab64;
    if (i < n) {
        int lab = load_label(labels, i, is64);
        int pos = atomicAdd(&g_cursor[lab], 1);
        g_sorted[pos] = i;
    }
}

// K5: per-class mean in registers (no atomics). Also reduces sq = sum(center^2).
__global__ void __launch_bounds__(D) k_classsum(const float* __restrict__ f) {
    int c = blockIdx.x;
    int t = threadIdx.x;  // column, 0..511
    int s = g_offsets[c], e = g_offsets[c + 1];
    int cnt = e - s;

    __shared__ int sidx[512];
    float acc0 = 0.f, acc1 = 0.f, acc2 = 0.f, acc3 = 0.f;

    for (int base = s; base < e; base += 512) {
        int m = e - base; if (m > 512) m = 512;
        __syncthreads();
        if (t < m) sidx[t] = g_sorted[base + t];
        __syncthreads();
        int r = 0;
        for (; r + 4 <= m; r += 4) {
            int i0 = sidx[r], i1 = sidx[r + 1], i2 = sidx[r + 2], i3 = sidx[r + 3];
            acc0 += f[i0 * D + t];
            acc1 += f[i1 * D + t];
            acc2 += f[i2 * D + t];
            acc3 += f[i3 * D + t];
        }
        for (; r < m; r++) acc0 += f[sidx[r] * D + t];
    }
    float acc = (acc0 + acc1) + (acc2 + acc3);
    float denom = fmaxf((float)cnt, 1.0f);
    float cen = acc / denom;
    g_centers[c * D + t] = cen;

    // tree-reduce cen^2 across 512 threads (order differs from pairwise dot — intentional,
    // matches the reference's independently-reduced sq vs matmul)
    float v = cen * cen;
#pragma unroll
    for (int off = 16; off > 0; off >>= 1)
        v += __shfl_down_sync(0xFFFFFFFF, v, off);
    __shared__ float ws[16];
    int warp = t >> 5, lane = t & 31;
    if (lane == 0) ws[warp] = v;
    __syncthreads();
    if (t < 16) {
        float w = ws[t];
#pragma unroll
        for (int off = 8; off > 0; off >>= 1)
            w += __shfl_down_sync(0xFFFF, w, off);
        if (t == 0) g_sq[c] = w;
    }
}

// K6: pairwise min over upper-triangle tiles. dis = sq[i]+sq[j]-2*dot (incl. diagonal,
// filtered by >0, same as reference).
#define PT 64
#define KC 64
__global__ void __launch_bounds__(256) k_pairwise() {
    int bi = blockIdx.x, bj = blockIdx.y;
    if (bj < bi) return;

    __shared__ float As[PT][KC + 1];
    __shared__ float Bs[PT][KC + 1];

    int tid = threadIdx.x;
    int tx = tid & 15;   // j micro index
    int ty = tid >> 4;   // i micro index

    float acc[4][4];
#pragma unroll
    for (int r = 0; r < 4; r++)
#pragma unroll
        for (int s2 = 0; s2 < 4; s2++) acc[r][s2] = 0.f;

    int rowb = tid >> 4;        // 0..15
    int kk   = (tid & 15) * 4;  // 0..60

    for (int k0 = 0; k0 < D; k0 += KC) {
        __syncthreads();
#pragma unroll
        for (int rr = 0; rr < 4; rr++) {
            int row = rowb + rr * 16;
            int gi = bi * PT + row;
            int gj = bj * PT + row;
            float4 av = (gi < NUM_CLASSES)
                ? *(const float4*)&g_centers[gi * D + k0 + kk]
                : make_float4(0.f, 0.f, 0.f, 0.f);
            float4 bv = (gj < NUM_CLASSES)
                ? *(const float4*)&g_centers[gj * D + k0 + kk]
                : make_float4(0.f, 0.f, 0.f, 0.f);
            As[row][kk] = av.x; As[row][kk + 1] = av.y; As[row][kk + 2] = av.z; As[row][kk + 3] = av.w;
            Bs[row][kk] = bv.x; Bs[row][kk + 1] = bv.y; Bs[row][kk + 2] = bv.z; Bs[row][kk + 3] = bv.w;
        }
        __syncthreads();
#pragma unroll
        for (int k = 0; k < KC; k++) {
            float a0 = As[ty * 4 + 0][k];
            float a1 = As[ty * 4 + 1][k];
            float a2 = As[ty * 4 + 2][k];
            float a3 = As[ty * 4 + 3][k];
            float b0 = Bs[tx * 4 + 0][k];
            float b1 = Bs[tx * 4 + 1][k];
            float b2 = Bs[tx * 4 + 2][k];
            float b3 = Bs[tx * 4 + 3][k];
            acc[0][0] += a0 * b0; acc[0][1] += a0 * b1; acc[0][2] += a0 * b2; acc[0][3] += a0 * b3;
            acc[1][0] += a1 * b0; acc[1][1] += a1 * b1; acc[1][2] += a1 * b2; acc[1][3] += a1 * b3;
            acc[2][0] += a2 * b0; acc[2][1] += a2 * b1; acc[2][2] += a2 * b2; acc[2][3] += a2 * b3;
            acc[3][0] += a3 * b0; acc[3][1] += a3 * b1; acc[3][2] += a3 * b2; acc[3][3] += a3 * b3;
        }
    }

    float lmin = __int_as_float(0x7F800000);
#pragma unroll
    for (int r = 0; r < 4; r++) {
        int gi = bi * PT + ty * 4 + r;
        if (gi >= NUM_CLASSES) continue;
        float sqi = g_sq[gi];
#pragma unroll
        for (int s2 = 0; s2 < 4; s2++) {
            int gj = bj * PT + tx * 4 + s2;
            if (gj >= NUM_CLASSES) continue;
            float dis = sqi + g_sq[gj] - 2.0f * acc[r][s2];
            if (dis > 0.0f) lmin = fminf(lmin, dis);
        }
    }
    if (lmin < __int_as_float(0x7F800000))
        atomicMin(&g_minbits, __float_as_int(lmin));
}

// K7: finalize
__global__ void k_final(float* out) {
    float d = __int_as_float(g_minbits);
    float l = fmaxf(1.0f - d, 0.0f);
    out[0] = l * 1.0f;  // BETA = 1.0
}

extern "C" void kernel_launch(void* const* d_in, const int* in_sizes, int n_in,
                              void* d_out, int out_size) {
    const float* features = (const float*)d_in[0];
    const void*  labels   = d_in[1];
    int n = in_sizes[1];
    float* out = (float*)d_out;

    k_init<<<1, 1024>>>();
    k_detect<<<1, 512>>>(labels);
    k_hist<<<(n + 255) / 256, 256>>>(labels, n);
    k_scan<<<1, 1024>>>(n);
    k_scatter<<<(n + 255) / 256, 256>>>(labels, n);
    k_classsum<<<NUM_CLASSES, D>>>(features);
    dim3 pg(16, 16);
    k_pairwise<<<pg, 256>>>();
    k_final<<<1, 1>>>(out);
}